// round 1
// baseline (speedup 1.0000x reference)
#include <cuda_runtime.h>
#include <math.h>

#define HH 128
#define WW 128
#define BB 8
#define CIN 64
#define COUT 64
#define HW (HH*WW)
#define NCH 27            // 18 offset channels + 9 mask channels
#define TP 32             // pixels per block in main kernel
#define CSTR 36           // colT row stride (padded, mult of 4)
#define SMEM_BYTES ((576*CSTR + 64*64)*4)

// scratch (allocation-free: device globals)
__device__ float g_om[BB*NCH*HW];       // offsets (ch 0..17) + mask=2*sigmoid (ch 18..26)
__device__ float g_wT[576*COUT];        // wT[ck][oc]

// ---------------------------------------------------------------------------
// Kernel 0: transpose main conv weight [oc][c][3][3] -> wT[ck][oc]
// ---------------------------------------------------------------------------
__global__ void transpose_w_kernel(const float* __restrict__ w) {
    int idx = blockIdx.x * 256 + threadIdx.x;
    if (idx < 576 * COUT) {
        int oc = idx / 576;
        int ck = idx % 576;
        g_wT[ck * COUT + oc] = w[idx];
    }
}

// ---------------------------------------------------------------------------
// Kernel 1: fused 3x3 conv producing 18 offsets + 9 masks (sigmoid applied)
// block = 128 threads = one W row; grid = (H, B)
// ---------------------------------------------------------------------------
__global__ void __launch_bounds__(128) conv_offmask_kernel(
    const float* __restrict__ data,
    const float* __restrict__ w_off, const float* __restrict__ b_off,
    const float* __restrict__ w_mod, const float* __restrict__ b_mod)
{
    __shared__ float ws[NCH * 32 * 9];   // 27*32*9 floats = 31104B
    const int h = blockIdx.x;
    const int b = blockIdx.y;
    const int x = threadIdx.x;

    float acc[NCH];
#pragma unroll
    for (int oc = 0; oc < 18; oc++) acc[oc] = b_off[oc];
#pragma unroll
    for (int oc = 0; oc < 9; oc++) acc[18 + oc] = b_mod[oc];

    for (int c0 = 0; c0 < CIN; c0 += 32) {
        __syncthreads();
        // stage weight chunk: ws[oc][cc][k]
        for (int idx = threadIdx.x; idx < NCH * 32 * 9; idx += 128) {
            int oc = idx / 288;
            int r  = idx % 288;     // cc*9+k
            const float* src = (oc < 18) ? (w_off + oc * 576) : (w_mod + (oc - 18) * 576);
            ws[idx] = src[c0 * 9 + r];
        }
        __syncthreads();

        for (int cc = 0; cc < 32; cc++) {
            const int c = c0 + cc;
            const float* dp = data + ((size_t)(b * CIN + c)) * HW;
            float d[9];
#pragma unroll
            for (int r = 0; r < 3; r++) {
                int hy = h - 1 + r;
                bool rok = (hy >= 0) && (hy < HH);
#pragma unroll
                for (int kx = 0; kx < 3; kx++) {
                    int wx = x - 1 + kx;
                    d[r * 3 + kx] = (rok && wx >= 0 && wx < WW) ? dp[hy * WW + wx] : 0.0f;
                }
            }
            const float* wrow = ws + cc * 9;
#pragma unroll
            for (int oc = 0; oc < NCH; oc++) {
                const float* wp = wrow + oc * 288;
                float s = d[0] * wp[0];
#pragma unroll
                for (int k = 1; k < 9; k++) s = fmaf(d[k], wp[k], s);
                acc[oc] += s;
            }
        }
    }

    float* outp = g_om + ((size_t)(b * NCH) * HH + h) * WW + x;
#pragma unroll
    for (int oc = 0; oc < NCH; oc++) {
        float v = acc[oc];
        if (oc >= 18) v = 2.0f / (1.0f + expf(-v));   // mask = 2*sigmoid
        outp[oc * HW] = v;
    }
}

// ---------------------------------------------------------------------------
// Kernel 2: deformable sampling (phase 1, im2col in smem) + GEMM (phase 2)
// block = 128 threads, TP=32 pixels (one h row segment), all 64 oc
// grid = (W/TP, H, B)
// ---------------------------------------------------------------------------
__global__ void __launch_bounds__(128) deform_main_kernel(
    const float* __restrict__ data,
    const float* __restrict__ bias,
    float* __restrict__ out)
{
    extern __shared__ float sm[];
    float* colT = sm;                 // [576][CSTR] : colT[ck][p]
    float* wsm  = sm + 576 * CSTR;    // [64][64]    : wsm[ckl][oc]

    const int w0  = blockIdx.x * TP;
    const int h   = blockIdx.y;
    const int b   = blockIdx.z;
    const int tid = threadIdx.x;

    // ---------------- phase 1: build sampled*mask columns ----------------
    const float* dbase = data + (size_t)b * CIN * HW;
    const float* omb   = g_om + ((size_t)(b * NCH) * HH + h) * WW;

    for (int q = tid; q < 9 * TP; q += 128) {
        const int t = q >> 5;         // tap 0..8
        const int p = q & 31;         // pixel 0..31
        const int x = w0 + p;

        const float dy = omb[(2 * t) * HW + x];
        const float dx = omb[(2 * t + 1) * HW + x];
        const float m  = omb[(18 + t) * HW + x];

        const float py = (float)(h - 1 + t / 3) + dy;
        const float px = (float)(x - 1 + t % 3) + dx;

        const float y0f = floorf(py), x0f = floorf(px);
        const float wy1 = py - y0f,  wx1 = px - x0f;
        const float wy0 = 1.0f - wy1, wx0 = 1.0f - wx1;

        const int y0 = (int)y0f, x0 = (int)x0f;
        const int y1 = y0 + 1,   x1 = x0 + 1;
        const bool vy0 = (y0 >= 0) && (y0 < HH);
        const bool vy1 = (y1 >= 0) && (y1 < HH);
        const bool vx0 = (x0 >= 0) && (x0 < WW);
        const bool vx1 = (x1 >= 0) && (x1 < WW);

        const float w00 = (vy0 && vx0) ? m * wy0 * wx0 : 0.0f;
        const float w01 = (vy0 && vx1) ? m * wy0 * wx1 : 0.0f;
        const float w10 = (vy1 && vx0) ? m * wy1 * wx0 : 0.0f;
        const float w11 = (vy1 && vx1) ? m * wy1 * wx1 : 0.0f;

        const int yc0 = min(max(y0, 0), HH - 1);
        const int yc1 = min(max(y1, 0), HH - 1);
        const int xc0 = min(max(x0, 0), WW - 1);
        const int xc1 = min(max(x1, 0), WW - 1);
        const int i00 = yc0 * WW + xc0;
        const int i01 = yc0 * WW + xc1;
        const int i10 = yc1 * WW + xc0;
        const int i11 = yc1 * WW + xc1;

        float* cp = colT + t * CSTR + p;      // advance by 9*CSTR per channel
#pragma unroll 4
        for (int c = 0; c < CIN; c++) {
            const float* d2 = dbase + c * HW;
            float v = w00 * d2[i00];
            v = fmaf(w01, d2[i01], v);
            v = fmaf(w10, d2[i10], v);
            v = fmaf(w11, d2[i11], v);
            cp[c * (9 * CSTR)] = v;
        }
    }
    __syncthreads();

    // ---------------- phase 2: GEMM 64oc x 32pix x 576 ----------------
    const int i   = tid >> 3;        // 0..15 -> oc group
    const int j   = tid & 7;         // 0..7  -> pixel group
    const int oc0 = i * 4;
    const int p0  = j * 4;

    float4 acc0 = make_float4(0.f, 0.f, 0.f, 0.f);
    float4 acc1 = make_float4(0.f, 0.f, 0.f, 0.f);
    float4 acc2 = make_float4(0.f, 0.f, 0.f, 0.f);
    float4 acc3 = make_float4(0.f, 0.f, 0.f, 0.f);

    for (int ch = 0; ch < 9; ch++) {
        // stage weight chunk wsm[ckl][oc] from wT (coalesced, conflict-free)
        for (int idx = tid; idx < 64 * 64; idx += 128)
            wsm[idx] = g_wT[ch * 64 * 64 + idx];
        __syncthreads();

        const float* cbase = colT + (ch * 64) * CSTR + p0;
#pragma unroll 8
        for (int kl = 0; kl < 64; kl++) {
            const float4 wv = *(const float4*)(wsm + kl * 64 + oc0);
            const float4 cv = *(const float4*)(cbase + kl * CSTR);
            acc0.x = fmaf(wv.x, cv.x, acc0.x);
            acc0.y = fmaf(wv.x, cv.y, acc0.y);
            acc0.z = fmaf(wv.x, cv.z, acc0.z);
            acc0.w = fmaf(wv.x, cv.w, acc0.w);
            acc1.x = fmaf(wv.y, cv.x, acc1.x);
            acc1.y = fmaf(wv.y, cv.y, acc1.y);
            acc1.z = fmaf(wv.y, cv.z, acc1.z);
            acc1.w = fmaf(wv.y, cv.w, acc1.w);
            acc2.x = fmaf(wv.z, cv.x, acc2.x);
            acc2.y = fmaf(wv.z, cv.y, acc2.y);
            acc2.z = fmaf(wv.z, cv.z, acc2.z);
            acc2.w = fmaf(wv.z, cv.w, acc2.w);
            acc3.x = fmaf(wv.w, cv.x, acc3.x);
            acc3.y = fmaf(wv.w, cv.y, acc3.y);
            acc3.z = fmaf(wv.w, cv.z, acc3.z);
            acc3.w = fmaf(wv.w, cv.w, acc3.w);
        }
        __syncthreads();
    }

    // ---------------- epilogue: bias + relu + float4 store ----------------
    float* ob = out + (((size_t)(b * COUT + oc0)) * HH + h) * WW + w0 + p0;
    {
        float bb = bias[oc0 + 0];
        float4 r = make_float4(fmaxf(acc0.x + bb, 0.f), fmaxf(acc0.y + bb, 0.f),
                               fmaxf(acc0.z + bb, 0.f), fmaxf(acc0.w + bb, 0.f));
        *(float4*)(ob + 0 * HW) = r;
    }
    {
        float bb = bias[oc0 + 1];
        float4 r = make_float4(fmaxf(acc1.x + bb, 0.f), fmaxf(acc1.y + bb, 0.f),
                               fmaxf(acc1.z + bb, 0.f), fmaxf(acc1.w + bb, 0.f));
        *(float4*)(ob + 1 * HW) = r;
    }
    {
        float bb = bias[oc0 + 2];
        float4 r = make_float4(fmaxf(acc2.x + bb, 0.f), fmaxf(acc2.y + bb, 0.f),
                               fmaxf(acc2.z + bb, 0.f), fmaxf(acc2.w + bb, 0.f));
        *(float4*)(ob + 2 * HW) = r;
    }
    {
        float bb = bias[oc0 + 3];
        float4 r = make_float4(fmaxf(acc3.x + bb, 0.f), fmaxf(acc3.y + bb, 0.f),
                               fmaxf(acc3.z + bb, 0.f), fmaxf(acc3.w + bb, 0.f));
        *(float4*)(ob + 3 * HW) = r;
    }
}

// ---------------------------------------------------------------------------
extern "C" void kernel_launch(void* const* d_in, const int* in_sizes, int n_in,
                              void* d_out, int out_size)
{
    const float* data  = (const float*)d_in[0];
    const float* w     = (const float*)d_in[1];
    const float* bias  = (const float*)d_in[2];
    const float* w_off = (const float*)d_in[3];
    const float* b_off = (const float*)d_in[4];
    const float* w_mod = (const float*)d_in[5];
    const float* b_mod = (const float*)d_in[6];
    float* out = (float*)d_out;

    cudaFuncSetAttribute(deform_main_kernel,
                         cudaFuncAttributeMaxDynamicSharedMemorySize, SMEM_BYTES);

    transpose_w_kernel<<<144, 256>>>(w);
    conv_offmask_kernel<<<dim3(HH, BB), 128>>>(data, w_off, b_off, w_mod, b_mod);
    deform_main_kernel<<<dim3(WW / TP, HH, BB), 128, SMEM_BYTES>>>(data, bias, out);
}

// round 2
// speedup vs baseline: 1.6724x; 1.6724x over previous
#include <cuda_runtime.h>
#include <math.h>
#include <stdint.h>

#define HH 128
#define WW 128
#define BB 8
#define CIN 64
#define COUT 64
#define HW (HH*WW)
#define NCH 27            // 18 offset channels + 9 mask channels
#define TP 64             // pixels per block in main kernel
#define CSTR 68           // colT row stride in floats (16B-aligned, conflict-safe)

// dynamic smem partition for deform kernel
#define OFF_WDUP 0
#define OFF_COLT (OFF_WDUP + 4096*8)              // 32768
#define OFF_MW   (OFF_COLT + 64*CSTR*4)           // +17408
#define OFF_MI   (OFF_MW   + 4*576*4)             // +9216
#define SMEM_BYTES (OFF_MI + 4*576*4)             // 68608

// scratch (allocation-free: device globals)
__device__ float    g_om[BB*NCH*HW];              // offsets + mask=2*sigmoid
__device__ uint64_t g_wTd[9*64*64];               // [tap][cin][oc] : (w,w) duplicated

// ---------------------------------------------------------------------------
// helpers: packed fp32x2
// ---------------------------------------------------------------------------
__device__ __forceinline__ uint64_t pack2(float lo, float hi) {
    uint64_t r;
    asm("mov.b64 %0, {%1,%2};" : "=l"(r)
        : "r"(__float_as_uint(lo)), "r"(__float_as_uint(hi)));
    return r;
}
__device__ __forceinline__ void unpack2(uint64_t v, float& lo, float& hi) {
    uint32_t a, b;
    asm("mov.b64 {%0,%1}, %2;" : "=r"(a), "=r"(b) : "l"(v));
    lo = __uint_as_float(a); hi = __uint_as_float(b);
}
#define FFMA2(acc, a, b) \
    asm("fma.rn.f32x2 %0, %1, %2, %0;" : "+l"(acc) : "l"(a), "l"(b))

// ---------------------------------------------------------------------------
// Kernel 0: weight transform [oc][c][3][3] -> g_wTd[(t*64+c)*64+oc] = (w,w)
// ---------------------------------------------------------------------------
__global__ void transpose_w_kernel(const float* __restrict__ w) {
    int idx = blockIdx.x * 256 + threadIdx.x;
    if (idx < 576 * COUT) {
        int oc  = idx / 576;
        int rem = idx % 576;
        int c   = rem / 9;
        int t   = rem % 9;
        float v = w[idx];
        g_wTd[(t * 64 + c) * 64 + oc] = pack2(v, v);
    }
}

// ---------------------------------------------------------------------------
// Kernel 1: fused 3x3 conv -> 18 offsets + 9 masks (2*sigmoid applied)
// FFMA2 over oc-pairs. block = 128 threads = one W row; grid = (H, B)
// ---------------------------------------------------------------------------
__global__ void __launch_bounds__(128) conv_offmask_kernel(
    const float* __restrict__ data,
    const float* __restrict__ w_off, const float* __restrict__ b_off,
    const float* __restrict__ w_mod, const float* __restrict__ b_mod)
{
    __shared__ uint64_t wsp[13 * 32 * 10];   // [pair][cc][k(pad10)] = (w2p, w2p+1)
    __shared__ float    wlast[32 * 10];      // oc=26 (mask ch 8)

    const int h = blockIdx.x;
    const int b = blockIdx.y;
    const int x = threadIdx.x;

    uint64_t acc2[13];
#pragma unroll
    for (int p = 0; p < 13; p++) {
        int ocA = 2 * p, ocB = 2 * p + 1;
        float bA = (ocA < 18) ? b_off[ocA] : b_mod[ocA - 18];
        float bB = (ocB < 18) ? b_off[ocB] : b_mod[ocB - 18];
        acc2[p] = pack2(bA, bB);
    }
    float acc26 = b_mod[8];

    for (int c0 = 0; c0 < CIN; c0 += 32) {
        __syncthreads();
        // stage paired+duplicated weights for this 32-channel chunk
        for (int idx = threadIdx.x; idx < 13 * 32 * 9; idx += 128) {
            int p  = idx / 288;
            int r  = idx % 288;
            int cc = r / 9;
            int k  = r % 9;
            int ocA = 2 * p, ocB = 2 * p + 1;
            const float* sA = (ocA < 18) ? (w_off + ocA * 576) : (w_mod + (ocA - 18) * 576);
            const float* sB = (ocB < 18) ? (w_off + ocB * 576) : (w_mod + (ocB - 18) * 576);
            wsp[(p * 32 + cc) * 10 + k] = pack2(sA[(c0 + cc) * 9 + k], sB[(c0 + cc) * 9 + k]);
        }
        for (int idx = threadIdx.x; idx < 32 * 9; idx += 128) {
            int cc = idx / 9, k = idx % 9;
            wlast[cc * 10 + k] = w_mod[8 * 576 + (c0 + cc) * 9 + k];
        }
        __syncthreads();

        for (int cc = 0; cc < 32; cc++) {
            const int c = c0 + cc;
            const float* dp = data + ((size_t)(b * CIN + c)) * HW;
            float d[9];
#pragma unroll
            for (int r = 0; r < 3; r++) {
                int hy = h - 1 + r;
                bool rok = (hy >= 0) && (hy < HH);
#pragma unroll
                for (int kx = 0; kx < 3; kx++) {
                    int wx = x - 1 + kx;
                    d[r * 3 + kx] = (rok && wx >= 0 && wx < WW) ? dp[hy * WW + wx] : 0.0f;
                }
            }
            uint64_t dd[9];
#pragma unroll
            for (int k = 0; k < 9; k++) dd[k] = pack2(d[k], d[k]);

#pragma unroll
            for (int p = 0; p < 13; p++) {
                const uint64_t* base = wsp + (p * 32 + cc) * 10;
                ulonglong2 w01 = *(const ulonglong2*)(base + 0);
                ulonglong2 w23 = *(const ulonglong2*)(base + 2);
                ulonglong2 w45 = *(const ulonglong2*)(base + 4);
                ulonglong2 w67 = *(const ulonglong2*)(base + 6);
                uint64_t   w8  = base[8];
                FFMA2(acc2[p], dd[0], w01.x);
                FFMA2(acc2[p], dd[1], w01.y);
                FFMA2(acc2[p], dd[2], w23.x);
                FFMA2(acc2[p], dd[3], w23.y);
                FFMA2(acc2[p], dd[4], w45.x);
                FFMA2(acc2[p], dd[5], w45.y);
                FFMA2(acc2[p], dd[6], w67.x);
                FFMA2(acc2[p], dd[7], w67.y);
                FFMA2(acc2[p], dd[8], w8);
            }
            const float* wl = wlast + cc * 10;
#pragma unroll
            for (int k = 0; k < 9; k++) acc26 = fmaf(d[k], wl[k], acc26);
        }
    }

    float* outp = g_om + ((size_t)(b * NCH) * HH + h) * WW + x;
#pragma unroll
    for (int p = 0; p < 13; p++) {
        float lo, hi;
        unpack2(acc2[p], lo, hi);
        int ocA = 2 * p, ocB = 2 * p + 1;
        if (ocA >= 18) lo = 2.0f / (1.0f + expf(-lo));
        if (ocB >= 18) hi = 2.0f / (1.0f + expf(-hi));
        outp[ocA * HW] = lo;
        outp[ocB * HW] = hi;
    }
    outp[26 * HW] = 2.0f / (1.0f + expf(-acc26));
}

// ---------------------------------------------------------------------------
// Kernel 2: deform sample + GEMM, chunked over 9 taps, FFMA2 inner loop.
// block = 128 threads, TP=64 pixels, all 64 oc. grid = (W/TP, H, B)
// ---------------------------------------------------------------------------
__global__ void __launch_bounds__(128) deform_main_kernel(
    const float* __restrict__ data,
    const float* __restrict__ bias,
    float* __restrict__ out)
{
    extern __shared__ char smx[];
    uint64_t* wdup = (uint64_t*)(smx + OFF_WDUP);   // [64 cin][64 oc] dup pairs
    float*    colT = (float*)   (smx + OFF_COLT);   // [64 cin][CSTR px]
    float*    mw   = (float*)   (smx + OFF_MW);     // 4 x [576] bilinear weights*mask
    int*      mi   = (int*)     (smx + OFF_MI);     // 4 x [576] gather indices

    const int w0  = blockIdx.x * TP;
    const int h   = blockIdx.y;
    const int b   = blockIdx.z;
    const int tid = threadIdx.x;

    const float* dbase = data + (size_t)b * CIN * HW;
    const float* omb   = g_om + ((size_t)(b * NCH) * HH + h) * WW;

    // ---- phase 0: bilinear metadata for all 9 taps x 64 pixels ----
    for (int q = tid; q < 9 * TP; q += 128) {
        const int t = q >> 6;
        const int p = q & (TP - 1);
        const int x = w0 + p;

        const float dy = omb[(2 * t) * HW + x];
        const float dx = omb[(2 * t + 1) * HW + x];
        const float m  = omb[(18 + t) * HW + x];

        const float py = (float)(h - 1 + t / 3) + dy;
        const float px = (float)(x - 1 + t % 3) + dx;

        const float y0f = floorf(py), x0f = floorf(px);
        const float wy1 = py - y0f,  wx1 = px - x0f;
        const float wy0 = 1.0f - wy1, wx0 = 1.0f - wx1;

        const int y0 = (int)y0f, x0 = (int)x0f;
        const int y1 = y0 + 1,   x1 = x0 + 1;
        const bool vy0 = (y0 >= 0) && (y0 < HH);
        const bool vy1 = (y1 >= 0) && (y1 < HH);
        const bool vx0 = (x0 >= 0) && (x0 < WW);
        const bool vx1 = (x1 >= 0) && (x1 < WW);

        mw[q]           = (vy0 && vx0) ? m * wy0 * wx0 : 0.0f;
        mw[576 + q]     = (vy0 && vx1) ? m * wy0 * wx1 : 0.0f;
        mw[2 * 576 + q] = (vy1 && vx0) ? m * wy1 * wx0 : 0.0f;
        mw[3 * 576 + q] = (vy1 && vx1) ? m * wy1 * wx1 : 0.0f;

        const int yc0 = min(max(y0, 0), HH - 1);
        const int yc1 = min(max(y1, 0), HH - 1);
        const int xc0 = min(max(x0, 0), WW - 1);
        const int xc1 = min(max(x1, 0), WW - 1);
        mi[q]           = yc0 * WW + xc0;
        mi[576 + q]     = yc0 * WW + xc1;
        mi[2 * 576 + q] = yc1 * WW + xc0;
        mi[3 * 576 + q] = yc1 * WW + xc1;
    }
    __syncthreads();

    // GEMM thread mapping
    const int i   = tid >> 3;          // 0..15 -> oc group of 4
    const int j   = tid & 7;           // 0..7  -> pixel groups {4j..4j+3, 32+4j..}
    const int oc0 = i * 4;

    uint64_t acc[4][4];
#pragma unroll
    for (int r = 0; r < 4; r++)
#pragma unroll
        for (int q = 0; q < 4; q++) acc[r][q] = 0ULL;

    const int gp = tid & 63;           // gather pixel
    const int gc = (tid >> 6) * 32;    // gather channel base (0 or 32)

    for (int ch = 0; ch < 9; ch++) {
        if (ch) __syncthreads();       // prev GEMM done before overwriting tiles

        // stage duplicated weights for this tap (coalesced u64)
        const uint64_t* wsrc = g_wTd + ch * 4096;
        for (int idx = tid; idx < 4096; idx += 128) wdup[idx] = wsrc[idx];

        // gather: 32 channels x 4 corners per thread
        const int q0 = ch * TP + gp;
        const float w00 = mw[q0];
        const float w01 = mw[576 + q0];
        const float w10 = mw[2 * 576 + q0];
        const float w11 = mw[3 * 576 + q0];
        const int i00 = mi[q0];
        const int i01 = mi[576 + q0];
        const int i10 = mi[2 * 576 + q0];
        const int i11 = mi[3 * 576 + q0];

        float* cp = colT + gc * CSTR + gp;
        const float* d2 = dbase + gc * HW;
#pragma unroll 8
        for (int c = 0; c < 32; c++) {
            float v = w00 * d2[i00];
            v = fmaf(w01, d2[i01], v);
            v = fmaf(w10, d2[i10], v);
            v = fmaf(w11, d2[i11], v);
            cp[c * CSTR] = v;
            d2 += HW;
        }
        __syncthreads();

        // GEMM: 64 oc x 64 px x 64 k (this tap), FFMA2
        const uint64_t* wrow = wdup + oc0;
        const float*    crow = colT + j * 4;
#pragma unroll 16
        for (int kl = 0; kl < 64; kl++) {
            ulonglong2 wa = *(const ulonglong2*)(wrow + kl * 64);       // oc0,oc0+1
            ulonglong2 wb = *(const ulonglong2*)(wrow + kl * 64 + 2);   // oc0+2,oc0+3
            ulonglong2 ca = *(const ulonglong2*)(crow + kl * CSTR);     // px 4j..4j+3
            ulonglong2 cb = *(const ulonglong2*)(crow + kl * CSTR + 32);// px 32+4j..
            FFMA2(acc[0][0], wa.x, ca.x); FFMA2(acc[0][1], wa.x, ca.y);
            FFMA2(acc[0][2], wa.x, cb.x); FFMA2(acc[0][3], wa.x, cb.y);
            FFMA2(acc[1][0], wa.y, ca.x); FFMA2(acc[1][1], wa.y, ca.y);
            FFMA2(acc[1][2], wa.y, cb.x); FFMA2(acc[1][3], wa.y, cb.y);
            FFMA2(acc[2][0], wb.x, ca.x); FFMA2(acc[2][1], wb.x, ca.y);
            FFMA2(acc[2][2], wb.x, cb.x); FFMA2(acc[2][3], wb.x, cb.y);
            FFMA2(acc[3][0], wb.y, ca.x); FFMA2(acc[3][1], wb.y, ca.y);
            FFMA2(acc[3][2], wb.y, cb.x); FFMA2(acc[3][3], wb.y, cb.y);
        }
    }

    // ---- epilogue: bias + relu + float4 stores ----
#pragma unroll
    for (int r = 0; r < 4; r++) {
        float bb = bias[oc0 + r];
        float* ob = out + (((size_t)(b * COUT + oc0 + r)) * HH + h) * WW + w0;
        float a0, a1, a2, a3;
        unpack2(acc[r][0], a0, a1);
        unpack2(acc[r][1], a2, a3);
        float4 r0 = make_float4(fmaxf(a0 + bb, 0.f), fmaxf(a1 + bb, 0.f),
                                fmaxf(a2 + bb, 0.f), fmaxf(a3 + bb, 0.f));
        *(float4*)(ob + j * 4) = r0;
        unpack2(acc[r][2], a0, a1);
        unpack2(acc[r][3], a2, a3);
        float4 r1 = make_float4(fmaxf(a0 + bb, 0.f), fmaxf(a1 + bb, 0.f),
                                fmaxf(a2 + bb, 0.f), fmaxf(a3 + bb, 0.f));
        *(float4*)(ob + 32 + j * 4) = r1;
    }
}

// ---------------------------------------------------------------------------
extern "C" void kernel_launch(void* const* d_in, const int* in_sizes, int n_in,
                              void* d_out, int out_size)
{
    const float* data  = (const float*)d_in[0];
    const float* w     = (const float*)d_in[1];
    const float* bias  = (const float*)d_in[2];
    const float* w_off = (const float*)d_in[3];
    const float* b_off = (const float*)d_in[4];
    const float* w_mod = (const float*)d_in[5];
    const float* b_mod = (const float*)d_in[6];
    float* out = (float*)d_out;

    cudaFuncSetAttribute(deform_main_kernel,
                         cudaFuncAttributeMaxDynamicSharedMemorySize, SMEM_BYTES);

    transpose_w_kernel<<<144, 256>>>(w);
    conv_offmask_kernel<<<dim3(HH, BB), 128>>>(data, w_off, b_off, w_mod, b_mod);
    deform_main_kernel<<<dim3(WW / TP, HH, BB), 128, SMEM_BYTES>>>(data, bias, out);
}

// round 4
// speedup vs baseline: 2.4827x; 1.4845x over previous
#include <cuda_runtime.h>
#include <math.h>
#include <stdint.h>

#define HH 128
#define WW 128
#define BB 8
#define CIN 64
#define COUT 64
#define HW (HH*WW)
#define NCH 27            // 18 offset channels + 9 mask channels
#define TP 64             // pixels per block in main kernel
#define CSTR 68           // colT row stride in floats (16B aligned, rotates banks)

// scratch (allocation-free: device globals)
__device__ float g_om[BB*NCH*HW];     // offsets + mask=2*sigmoid
__device__ float g_wT[9*64*64];       // [tap][cin][oc]

// ---------------------------------------------------------------------------
// packed fp32x2 helpers
// ---------------------------------------------------------------------------
__device__ __forceinline__ uint64_t pack2(float lo, float hi) {
    uint64_t r;
    asm("mov.b64 %0, {%1,%2};" : "=l"(r)
        : "r"(__float_as_uint(lo)), "r"(__float_as_uint(hi)));
    return r;
}
__device__ __forceinline__ void unpack2(uint64_t v, float& lo, float& hi) {
    uint32_t a, b;
    asm("mov.b64 {%0,%1}, %2;" : "=r"(a), "=r"(b) : "l"(v));
    lo = __uint_as_float(a); hi = __uint_as_float(b);
}
#define FFMA2(acc, a, b) \
    asm("fma.rn.f32x2 %0, %1, %2, %0;" : "+l"(acc) : "l"(a), "l"(b))

// ---------------------------------------------------------------------------
// Kernel 0: weight transform [oc][c][3][3] -> g_wT[t][c][oc]
// ---------------------------------------------------------------------------
__global__ void transpose_w_kernel(const float* __restrict__ w) {
    int idx = blockIdx.x * 256 + threadIdx.x;
    if (idx < 576 * COUT) {
        int oc  = idx / 576;
        int rem = idx % 576;
        int c   = rem / 9;
        int t   = rem % 9;
        g_wT[t * 4096 + c * 64 + oc] = w[idx];
    }
}

// ---------------------------------------------------------------------------
// Kernel 1: fused 3x3 conv -> 18 offsets + 9 masks (2*sigmoid). FFMA2 oc-pairs.
// block = 128 threads = one W row; grid = (H, B)
// ---------------------------------------------------------------------------
__global__ void __launch_bounds__(128) conv_offmask_kernel(
    const float* __restrict__ data,
    const float* __restrict__ w_off, const float* __restrict__ b_off,
    const float* __restrict__ w_mod, const float* __restrict__ b_mod)
{
    __shared__ uint64_t wsp[13 * 32 * 10];
    __shared__ float    wlast[32 * 10];

    const int h = blockIdx.x;
    const int b = blockIdx.y;
    const int x = threadIdx.x;

    uint64_t acc2[13];
#pragma unroll
    for (int p = 0; p < 13; p++) {
        int ocA = 2 * p, ocB = 2 * p + 1;
        float bA = (ocA < 18) ? b_off[ocA] : b_mod[ocA - 18];
        float bB = (ocB < 18) ? b_off[ocB] : b_mod[ocB - 18];
        acc2[p] = pack2(bA, bB);
    }
    float acc26 = b_mod[8];

    for (int c0 = 0; c0 < CIN; c0 += 32) {
        __syncthreads();
        for (int idx = threadIdx.x; idx < 13 * 32 * 9; idx += 128) {
            int p  = idx / 288;
            int r  = idx % 288;
            int cc = r / 9;
            int k  = r % 9;
            int ocA = 2 * p, ocB = 2 * p + 1;
            const float* sA = (ocA < 18) ? (w_off + ocA * 576) : (w_mod + (ocA - 18) * 576);
            const float* sB = (ocB < 18) ? (w_off + ocB * 576) : (w_mod + (ocB - 18) * 576);
            wsp[(p * 32 + cc) * 10 + k] = pack2(sA[(c0 + cc) * 9 + k], sB[(c0 + cc) * 9 + k]);
        }
        for (int idx = threadIdx.x; idx < 32 * 9; idx += 128) {
            int cc = idx / 9, k = idx % 9;
            wlast[cc * 10 + k] = w_mod[8 * 576 + (c0 + cc) * 9 + k];
        }
        __syncthreads();

        for (int cc = 0; cc < 32; cc++) {
            const int c = c0 + cc;
            const float* dp = data + ((size_t)(b * CIN + c)) * HW;
            float d[9];
#pragma unroll
            for (int r = 0; r < 3; r++) {
                int hy = h - 1 + r;
                bool rok = (hy >= 0) && (hy < HH);
#pragma unroll
                for (int kx = 0; kx < 3; kx++) {
                    int wx = x - 1 + kx;
                    d[r * 3 + kx] = (rok && wx >= 0 && wx < WW) ? dp[hy * WW + wx] : 0.0f;
                }
            }
            uint64_t dd[9];
#pragma unroll
            for (int k = 0; k < 9; k++) dd[k] = pack2(d[k], d[k]);

#pragma unroll
            for (int p = 0; p < 13; p++) {
                const uint64_t* base = wsp + (p * 32 + cc) * 10;
                ulonglong2 w01 = *(const ulonglong2*)(base + 0);
                ulonglong2 w23 = *(const ulonglong2*)(base + 2);
                ulonglong2 w45 = *(const ulonglong2*)(base + 4);
                ulonglong2 w67 = *(const ulonglong2*)(base + 6);
                uint64_t   w8  = base[8];
                FFMA2(acc2[p], dd[0], w01.x);
                FFMA2(acc2[p], dd[1], w01.y);
                FFMA2(acc2[p], dd[2], w23.x);
                FFMA2(acc2[p], dd[3], w23.y);
                FFMA2(acc2[p], dd[4], w45.x);
                FFMA2(acc2[p], dd[5], w45.y);
                FFMA2(acc2[p], dd[6], w67.x);
                FFMA2(acc2[p], dd[7], w67.y);
                FFMA2(acc2[p], dd[8], w8);
            }
            const float* wl = wlast + cc * 10;
#pragma unroll
            for (int k = 0; k < 9; k++) acc26 = fmaf(d[k], wl[k], acc26);
        }
    }

    float* outp = g_om + ((size_t)(b * NCH) * HH + h) * WW + x;
#pragma unroll
    for (int p = 0; p < 13; p++) {
        float lo, hi;
        unpack2(acc2[p], lo, hi);
        int ocA = 2 * p, ocB = 2 * p + 1;
        if (ocA >= 18) lo = 2.0f / (1.0f + expf(-lo));
        if (ocB >= 18) hi = 2.0f / (1.0f + expf(-hi));
        outp[ocA * HW] = lo;
        outp[ocB * HW] = hi;
    }
    outp[26 * HW] = 2.0f / (1.0f + expf(-acc26));
}

// ---------------------------------------------------------------------------
// Kernel 2: deform sample + GEMM, tap-chunked, FFMA2, oc-pair register tile.
// block = 128 threads, TP=64 px, 64 oc. smem = 33.8KB -> 5 blocks/SM.
// grid = (W/TP, H, B)
// ---------------------------------------------------------------------------
__global__ void __launch_bounds__(128, 5) deform_main_kernel(
    const float* __restrict__ data,
    const float* __restrict__ bias,
    float* __restrict__ out)
{
    __shared__ float wsm[4096];          // [cin][oc] for current tap
    __shared__ float colT[64 * CSTR];    // [cin][px]

    const int w0  = blockIdx.x * TP;
    const int h   = blockIdx.y;
    const int b   = blockIdx.z;
    const int tid = threadIdx.x;

    const float* dbase = data + (size_t)b * CIN * HW;
    const float* omb   = g_om + ((size_t)(b * NCH) * HH + h) * WW;

    // GEMM mapping: 8 ocs x 4 px per thread
    const int i   = tid >> 4;            // 0..7  -> oc base i*8
    const int j   = tid & 15;            // 0..15 -> px base j*4
    const int oc0 = i * 8;

    // gather mapping: pixel p, channel half gc
    const int gp = tid & 63;
    const int gc = (tid >> 6) * 32;
    const int x  = w0 + gp;

    uint64_t acc[4][4];                  // [oc pair][px]
#pragma unroll
    for (int p = 0; p < 4; p++)
#pragma unroll
        for (int q = 0; q < 4; q++) acc[p][q] = 0ULL;

    for (int t = 0; t < 9; t++) {
        if (t) __syncthreads();          // prev GEMM done before overwrite

        // stage this tap's weights (16KB, float4)
        {
            const float4* bsrc = (const float4*)(g_wT + t * 4096);
            float4* bdst = (float4*)wsm;
#pragma unroll
            for (int r = 0; r < 8; r++) bdst[tid + r * 128] = bsrc[tid + r * 128];
        }

        // bilinear metadata for this thread's pixel (inline, no smem)
        const float dy = omb[(2 * t) * HW + x];
        const float dx = omb[(2 * t + 1) * HW + x];
        const float mk = omb[(18 + t) * HW + x];

        const float py = (float)(h - 1 + t / 3) + dy;
        const float px = (float)(x - 1 + t % 3) + dx;

        const float y0f = floorf(py), x0f = floorf(px);
        const float wy1 = py - y0f,  wx1 = px - x0f;
        const float wy0 = 1.0f - wy1, wx0 = 1.0f - wx1;

        const int y0 = (int)y0f, x0 = (int)x0f;
        const int y1 = y0 + 1,   x1 = x0 + 1;
        const bool vy0 = (y0 >= 0) && (y0 < HH);
        const bool vy1 = (y1 >= 0) && (y1 < HH);
        const bool vx0 = (x0 >= 0) && (x0 < WW);
        const bool vx1 = (x1 >= 0) && (x1 < WW);

        const float w00 = (vy0 && vx0) ? mk * wy0 * wx0 : 0.0f;
        const float w01 = (vy0 && vx1) ? mk * wy0 * wx1 : 0.0f;
        const float w10 = (vy1 && vx0) ? mk * wy1 * wx0 : 0.0f;
        const float w11 = (vy1 && vx1) ? mk * wy1 * wx1 : 0.0f;

        const int yc0 = min(max(y0, 0), HH - 1);
        const int yc1 = min(max(y1, 0), HH - 1);
        const int xc0 = min(max(x0, 0), WW - 1);
        const int xc1 = min(max(x1, 0), WW - 1);
        const int i00 = yc0 * WW + xc0;
        const int i01 = yc0 * WW + xc1;
        const int i10 = yc1 * WW + xc0;
        const int i11 = yc1 * WW + xc1;

        // gather 32 channels for this pixel
        const float* d2 = dbase + (size_t)gc * HW;
        float* cp = colT + gc * CSTR + gp;
#pragma unroll 8
        for (int cc = 0; cc < 32; cc++) {
            float v = w00 * d2[i00];
            v = fmaf(w01, d2[i01], v);
            v = fmaf(w10, d2[i10], v);
            v = fmaf(w11, d2[i11], v);
            cp[cc * CSTR] = v;
            d2 += HW;
        }
        __syncthreads();

        // GEMM: 64 k for this tap
        const float* wrow = wsm + oc0;
        const float* crow = colT + j * 4;
#pragma unroll 8
        for (int kl = 0; kl < 64; kl++) {
            ulonglong2 wA = *(const ulonglong2*)(wrow + kl * 64);      // oc 0-3
            ulonglong2 wB = *(const ulonglong2*)(wrow + kl * 64 + 4);  // oc 4-7
            float4 cv = *(const float4*)(crow + kl * CSTR);            // px 0-3
            uint64_t c0 = pack2(cv.x, cv.x);
            uint64_t c1 = pack2(cv.y, cv.y);
            uint64_t c2 = pack2(cv.z, cv.z);
            uint64_t c3 = pack2(cv.w, cv.w);
            FFMA2(acc[0][0], wA.x, c0); FFMA2(acc[0][1], wA.x, c1);
            FFMA2(acc[0][2], wA.x, c2); FFMA2(acc[0][3], wA.x, c3);
            FFMA2(acc[1][0], wA.y, c0); FFMA2(acc[1][1], wA.y, c1);
            FFMA2(acc[1][2], wA.y, c2); FFMA2(acc[1][3], wA.y, c3);
            FFMA2(acc[2][0], wB.x, c0); FFMA2(acc[2][1], wB.x, c1);
            FFMA2(acc[2][2], wB.x, c2); FFMA2(acc[2][3], wB.x, c3);
            FFMA2(acc[3][0], wB.y, c0); FFMA2(acc[3][1], wB.y, c1);
            FFMA2(acc[3][2], wB.y, c2); FFMA2(acc[3][3], wB.y, c3);
        }
    }

    // ---- epilogue: bias + relu + float4 stores (4 px per oc per thread) ----
#pragma unroll
    for (int p = 0; p < 4; p++) {
        const int ocA = oc0 + 2 * p;
        const float bA = bias[ocA];
        const float bB = bias[ocA + 1];
        float a0, b0, a1, b1, a2, b2, a3, b3;
        unpack2(acc[p][0], a0, b0);
        unpack2(acc[p][1], a1, b1);
        unpack2(acc[p][2], a2, b2);
        unpack2(acc[p][3], a3, b3);
        float* obA = out + (((size_t)(b * COUT + ocA)) * HH + h) * WW + w0 + j * 4;
        float4 rA = make_float4(fmaxf(a0 + bA, 0.f), fmaxf(a1 + bA, 0.f),
                                fmaxf(a2 + bA, 0.f), fmaxf(a3 + bA, 0.f));
        *(float4*)obA = rA;
        float4 rB = make_float4(fmaxf(b0 + bB, 0.f), fmaxf(b1 + bB, 0.f),
                                fmaxf(b2 + bB, 0.f), fmaxf(b3 + bB, 0.f));
        *(float4*)(obA + HW) = rB;
    }
}

// ---------------------------------------------------------------------------
extern "C" void kernel_launch(void* const* d_in, const int* in_sizes, int n_in,
                              void* d_out, int out_size)
{
    const float* data  = (const float*)d_in[0];
    const float* w     = (const float*)d_in[1];
    const float* bias  = (const float*)d_in[2];
    const float* w_off = (const float*)d_in[3];
    const float* b_off = (const float*)d_in[4];
    const float* w_mod = (const float*)d_in[5];
    const float* b_mod = (const float*)d_in[6];
    float* out = (float*)d_out;

    conv_offmask_kernel<<<dim3(HH, BB), 128>>>(data, w_off, b_off, w_mod, b_mod);
    transpose_w_kernel<<<144, 256>>>(w);
    deform_main_kernel<<<dim3(WW / TP, HH, BB), 128>>>(data, bias, out);
}

// round 5
// speedup vs baseline: 2.6866x; 1.0821x over previous
#include <cuda_runtime.h>
#include <math.h>
#include <stdint.h>

#define HH 128
#define WW 128
#define BB 8
#define CIN 64
#define COUT 64
#define HW (HH*WW)
#define NCH 27            // 18 offset channels + 9 mask channels
#define TP 64             // pixels per block in main kernel
#define CSTR 68           // colT row stride in floats

// scratch (allocation-free: device globals)
__device__ float g_om[BB*NCH*HW];     // offsets + mask=2*sigmoid
__device__ float g_wT[9*64*64];       // [tap][cin][oc]

// ---------------------------------------------------------------------------
// packed fp32x2 helpers
// ---------------------------------------------------------------------------
__device__ __forceinline__ uint64_t pack2(float lo, float hi) {
    uint64_t r;
    asm("mov.b64 %0, {%1,%2};" : "=l"(r)
        : "r"(__float_as_uint(lo)), "r"(__float_as_uint(hi)));
    return r;
}
__device__ __forceinline__ void unpack2(uint64_t v, float& lo, float& hi) {
    uint32_t a, b;
    asm("mov.b64 {%0,%1}, %2;" : "=r"(a), "=r"(b) : "l"(v));
    lo = __uint_as_float(a); hi = __uint_as_float(b);
}
#define FFMA2(acc, a, b) \
    asm("fma.rn.f32x2 %0, %1, %2, %0;" : "+l"(acc) : "l"(a), "l"(b))

// ---------------------------------------------------------------------------
// Kernel 0: weight transform [oc][c][3][3] -> g_wT[t][c][oc]
// ---------------------------------------------------------------------------
__global__ void transpose_w_kernel(const float* __restrict__ w) {
    int idx = blockIdx.x * 256 + threadIdx.x;
    if (idx < 576 * COUT) {
        int oc  = idx / 576;
        int rem = idx % 576;
        int c   = rem / 9;
        int t   = rem % 9;
        g_wT[t * 4096 + c * 64 + oc] = w[idx];
    }
}

// ---------------------------------------------------------------------------
// Kernel 1: fused 3x3 conv -> 18 offsets + 9 masks (2*sigmoid).
// 2 output rows per block, smem-staged data, FFMA2 oc-pairs.
// block = 128 threads; grid = (H/2, B). dynamic smem 51.5KB.
// ---------------------------------------------------------------------------
#define WSP_U64   (13*32*10)                  // 4160 u64 = 33280 B
#define OFFC_WLAST (WSP_U64*8)                // 33280
#define OFFC_DT   (OFFC_WLAST + 32*10*4)      // 34560
#define CSM_BYTES (OFFC_DT + 8*4*132*4)       // 51456

__global__ void __launch_bounds__(128, 4) conv_offmask_kernel(
    const float* __restrict__ data,
    const float* __restrict__ w_off, const float* __restrict__ b_off,
    const float* __restrict__ w_mod, const float* __restrict__ b_mod)
{
    extern __shared__ char csm[];
    uint64_t* wsp   = (uint64_t*)csm;
    float*    wlast = (float*)(csm + OFFC_WLAST);
    float*    dtile = (float*)(csm + OFFC_DT);    // [8ch][4row][132]

    const int h0 = blockIdx.x * 2;
    const int b  = blockIdx.y;
    const int x  = threadIdx.x;

    // zero halo columns once
    if (threadIdx.x < 64) {
        int q = threadIdx.x >> 3;
        int r = (threadIdx.x >> 1) & 3;
        int s = threadIdx.x & 1;
        dtile[q * 528 + r * 132 + s * 129] = 0.0f;
    }

    uint64_t acc2[2][13];
#pragma unroll
    for (int p = 0; p < 13; p++) {
        int ocA = 2 * p, ocB = 2 * p + 1;
        float bA = (ocA < 18) ? b_off[ocA] : b_mod[ocA - 18];
        float bB = (ocB < 18) ? b_off[ocB] : b_mod[ocB - 18];
        acc2[0][p] = pack2(bA, bB);
        acc2[1][p] = acc2[0][p];
    }
    float acc26_0 = b_mod[8];
    float acc26_1 = b_mod[8];

    for (int c0 = 0; c0 < CIN; c0 += 32) {
        __syncthreads();      // all compute on previous chunk's wsp done
        // stage paired weights for this 32-channel chunk
        for (int idx = threadIdx.x; idx < 13 * 32 * 9; idx += 128) {
            int p  = idx / 288;
            int r  = idx % 288;
            int cc = r / 9;
            int k  = r % 9;
            int ocA = 2 * p, ocB = 2 * p + 1;
            const float* sA = (ocA < 18) ? (w_off + ocA * 576) : (w_mod + (ocA - 18) * 576);
            const float* sB = (ocB < 18) ? (w_off + ocB * 576) : (w_mod + (ocB - 18) * 576);
            wsp[(p * 32 + cc) * 10 + k] = pack2(sA[(c0 + cc) * 9 + k], sB[(c0 + cc) * 9 + k]);
        }
        for (int idx = threadIdx.x; idx < 32 * 9; idx += 128) {
            int cc = idx / 9, k = idx % 9;
            wlast[cc * 10 + k] = w_mod[8 * 576 + (c0 + cc) * 9 + k];
        }

        for (int cg = 0; cg < 4; cg++) {
            __syncthreads();   // prev compute done before dtile overwrite
            // stage 8 channels x 4 rows into smem (coalesced)
            const int cb = c0 + cg * 8;
#pragma unroll
            for (int q = 0; q < 8; q++) {
                const float* dp = data + ((size_t)(b * CIN + cb + q)) * HW;
#pragma unroll
                for (int r = 0; r < 4; r++) {
                    int hy = h0 - 1 + r;
                    float v = 0.0f;
                    if (hy >= 0 && hy < HH) v = dp[hy * WW + x];
                    dtile[q * 528 + r * 132 + 1 + x] = v;
                }
            }
            __syncthreads();

#pragma unroll
            for (int q = 0; q < 8; q++) {
                const int cc = cg * 8 + q;
                const float* dp = dtile + q * 528 + x;   // [r*132 + kx] (halo built in)
                // 12 unique tap values, dup-packed
                uint64_t dup[4][3];
                float    dsc[4][3];
#pragma unroll
                for (int r = 0; r < 4; r++)
#pragma unroll
                    for (int kx = 0; kx < 3; kx++) {
                        float v = dp[r * 132 + kx];
                        dsc[r][kx] = v;
                        dup[r][kx] = pack2(v, v);
                    }

#pragma unroll
                for (int p = 0; p < 13; p++) {
                    const uint64_t* base = wsp + (p * 32 + cc) * 10;
                    ulonglong2 w01 = *(const ulonglong2*)(base + 0);
                    ulonglong2 w23 = *(const ulonglong2*)(base + 2);
                    ulonglong2 w45 = *(const ulonglong2*)(base + 4);
                    ulonglong2 w67 = *(const ulonglong2*)(base + 6);
                    uint64_t   w8  = base[8];
                    // row 0 output (rows 0..2)
                    FFMA2(acc2[0][p], dup[0][0], w01.x);
                    FFMA2(acc2[0][p], dup[0][1], w01.y);
                    FFMA2(acc2[0][p], dup[0][2], w23.x);
                    FFMA2(acc2[0][p], dup[1][0], w23.y);
                    FFMA2(acc2[0][p], dup[1][1], w45.x);
                    FFMA2(acc2[0][p], dup[1][2], w45.y);
                    FFMA2(acc2[0][p], dup[2][0], w67.x);
                    FFMA2(acc2[0][p], dup[2][1], w67.y);
                    FFMA2(acc2[0][p], dup[2][2], w8);
                    // row 1 output (rows 1..3)
                    FFMA2(acc2[1][p], dup[1][0], w01.x);
                    FFMA2(acc2[1][p], dup[1][1], w01.y);
                    FFMA2(acc2[1][p], dup[1][2], w23.x);
                    FFMA2(acc2[1][p], dup[2][0], w23.y);
                    FFMA2(acc2[1][p], dup[2][1], w45.x);
                    FFMA2(acc2[1][p], dup[2][2], w45.y);
                    FFMA2(acc2[1][p], dup[3][0], w67.x);
                    FFMA2(acc2[1][p], dup[3][1], w67.y);
                    FFMA2(acc2[1][p], dup[3][2], w8);
                }
                const float* wl = wlast + cc * 10;
#pragma unroll
                for (int k = 0; k < 9; k++) {
                    acc26_0 = fmaf(dsc[k / 3][k % 3],     wl[k], acc26_0);
                    acc26_1 = fmaf(dsc[k / 3 + 1][k % 3], wl[k], acc26_1);
                }
            }
        }
    }

#pragma unroll
    for (int rr = 0; rr < 2; rr++) {
        float* outp = g_om + ((size_t)(b * NCH) * HH + (h0 + rr)) * WW + x;
#pragma unroll
        for (int p = 0; p < 13; p++) {
            float lo, hi;
            unpack2(acc2[rr][p], lo, hi);
            int ocA = 2 * p, ocB = 2 * p + 1;
            if (ocA >= 18) lo = 2.0f / (1.0f + expf(-lo));
            if (ocB >= 18) hi = 2.0f / (1.0f + expf(-hi));
            outp[ocA * HW] = lo;
            outp[ocB * HW] = hi;
        }
        float a26 = rr ? acc26_1 : acc26_0;
        outp[26 * HW] = 2.0f / (1.0f + expf(-a26));
    }
}

// ---------------------------------------------------------------------------
// Kernel 2: deform sample + GEMM, tap-chunked, FFMA2, oc-pair register tile.
// block = 128 threads, TP=64 px, 64 oc. smem = 33.8KB -> 5 blocks/SM.
// grid = (W/TP, H, B)
// ---------------------------------------------------------------------------
__global__ void __launch_bounds__(128, 5) deform_main_kernel(
    const float* __restrict__ data,
    const float* __restrict__ bias,
    float* __restrict__ out)
{
    __shared__ float wsm[4096];          // [cin][oc] for current tap
    __shared__ float colT[64 * CSTR];    // [cin][px]

    const int w0  = blockIdx.x * TP;
    const int h   = blockIdx.y;
    const int b   = blockIdx.z;
    const int tid = threadIdx.x;

    const float* dbase = data + (size_t)b * CIN * HW;
    const float* omb   = g_om + ((size_t)(b * NCH) * HH + h) * WW;

    const int i   = tid >> 4;            // 0..7  -> oc base i*8
    const int j   = tid & 15;            // 0..15 -> px base j*4
    const int oc0 = i * 8;

    const int gp = tid & 63;
    const int gc = (tid >> 6) * 32;
    const int x  = w0 + gp;

    uint64_t acc[4][4];                  // [oc pair][px]
#pragma unroll
    for (int p = 0; p < 4; p++)
#pragma unroll
        for (int q = 0; q < 4; q++) acc[p][q] = 0ULL;

    for (int t = 0; t < 9; t++) {
        if (t) __syncthreads();

        {
            const float4* bsrc = (const float4*)(g_wT + t * 4096);
            float4* bdst = (float4*)wsm;
#pragma unroll
            for (int r = 0; r < 8; r++) bdst[tid + r * 128] = bsrc[tid + r * 128];
        }

        const float dy = omb[(2 * t) * HW + x];
        const float dx = omb[(2 * t + 1) * HW + x];
        const float mk = omb[(18 + t) * HW + x];

        const float py = (float)(h - 1 + t / 3) + dy;
        const float px = (float)(x - 1 + t % 3) + dx;

        const float y0f = floorf(py), x0f = floorf(px);
        const float wy1 = py - y0f,  wx1 = px - x0f;
        const float wy0 = 1.0f - wy1, wx0 = 1.0f - wx1;

        const int y0 = (int)y0f, x0 = (int)x0f;
        const int y1 = y0 + 1,   x1 = x0 + 1;
        const bool vy0 = (y0 >= 0) && (y0 < HH);
        const bool vy1 = (y1 >= 0) && (y1 < HH);
        const bool vx0 = (x0 >= 0) && (x0 < WW);
        const bool vx1 = (x1 >= 0) && (x1 < WW);

        const float w00 = (vy0 && vx0) ? mk * wy0 * wx0 : 0.0f;
        const float w01 = (vy0 && vx1) ? mk * wy0 * wx1 : 0.0f;
        const float w10 = (vy1 && vx0) ? mk * wy1 * wx0 : 0.0f;
        const float w11 = (vy1 && vx1) ? mk * wy1 * wx1 : 0.0f;

        const int yc0 = min(max(y0, 0), HH - 1);
        const int yc1 = min(max(y1, 0), HH - 1);
        const int xc0 = min(max(x0, 0), WW - 1);
        const int xc1 = min(max(x1, 0), WW - 1);
        const int i00 = yc0 * WW + xc0;
        const int i01 = yc0 * WW + xc1;
        const int i10 = yc1 * WW + xc0;
        const int i11 = yc1 * WW + xc1;

        const float* d2 = dbase + (size_t)gc * HW;
        float* cp = colT + gc * CSTR + gp;
#pragma unroll 8
        for (int cc = 0; cc < 32; cc++) {
            float v = w00 * d2[i00];
            v = fmaf(w01, d2[i01], v);
            v = fmaf(w10, d2[i10], v);
            v = fmaf(w11, d2[i11], v);
            cp[cc * CSTR] = v;
            d2 += HW;
        }
        __syncthreads();

        const float* wrow = wsm + oc0;
        const float* crow = colT + j * 4;
#pragma unroll 8
        for (int kl = 0; kl < 64; kl++) {
            ulonglong2 wA = *(const ulonglong2*)(wrow + kl * 64);
            ulonglong2 wB = *(const ulonglong2*)(wrow + kl * 64 + 4);
            float4 cv = *(const float4*)(crow + kl * CSTR);
            uint64_t c0 = pack2(cv.x, cv.x);
            uint64_t c1 = pack2(cv.y, cv.y);
            uint64_t c2 = pack2(cv.z, cv.z);
            uint64_t c3 = pack2(cv.w, cv.w);
            FFMA2(acc[0][0], wA.x, c0); FFMA2(acc[0][1], wA.x, c1);
            FFMA2(acc[0][2], wA.x, c2); FFMA2(acc[0][3], wA.x, c3);
            FFMA2(acc[1][0], wA.y, c0); FFMA2(acc[1][1], wA.y, c1);
            FFMA2(acc[1][2], wA.y, c2); FFMA2(acc[1][3], wA.y, c3);
            FFMA2(acc[2][0], wB.x, c0); FFMA2(acc[2][1], wB.x, c1);
            FFMA2(acc[2][2], wB.x, c2); FFMA2(acc[2][3], wB.x, c3);
            FFMA2(acc[3][0], wB.y, c0); FFMA2(acc[3][1], wB.y, c1);
            FFMA2(acc[3][2], wB.y, c2); FFMA2(acc[3][3], wB.y, c3);
        }
    }

#pragma unroll
    for (int p = 0; p < 4; p++) {
        const int ocA = oc0 + 2 * p;
        const float bA = bias[ocA];
        const float bB = bias[ocA + 1];
        float a0, b0, a1, b1, a2, b2, a3, b3;
        unpack2(acc[p][0], a0, b0);
        unpack2(acc[p][1], a1, b1);
        unpack2(acc[p][2], a2, b2);
        unpack2(acc[p][3], a3, b3);
        float* obA = out + (((size_t)(b * COUT + ocA)) * HH + h) * WW + w0 + j * 4;
        float4 rA = make_float4(fmaxf(a0 + bA, 0.f), fmaxf(a1 + bA, 0.f),
                                fmaxf(a2 + bA, 0.f), fmaxf(a3 + bA, 0.f));
        *(float4*)obA = rA;
        float4 rB = make_float4(fmaxf(b0 + bB, 0.f), fmaxf(b1 + bB, 0.f),
                                fmaxf(b2 + bB, 0.f), fmaxf(b3 + bB, 0.f));
        *(float4*)(obA + HW) = rB;
    }
}

// ---------------------------------------------------------------------------
extern "C" void kernel_launch(void* const* d_in, const int* in_sizes, int n_in,
                              void* d_out, int out_size)
{
    const float* data  = (const float*)d_in[0];
    const float* w     = (const float*)d_in[1];
    const float* bias  = (const float*)d_in[2];
    const float* w_off = (const float*)d_in[3];
    const float* b_off = (const float*)d_in[4];
    const float* w_mod = (const float*)d_in[5];
    const float* b_mod = (const float*)d_in[6];
    float* out = (float*)d_out;

    cudaFuncSetAttribute(conv_offmask_kernel,
                         cudaFuncAttributeMaxDynamicSharedMemorySize, CSM_BYTES);

    conv_offmask_kernel<<<dim3(HH / 2, BB), 128, CSM_BYTES>>>(data, w_off, b_off, w_mod, b_mod);
    transpose_w_kernel<<<144, 256>>>(w);
    deform_main_kernel<<<dim3(WW / TP, HH, BB), 128>>>(data, bias, out);
}

// round 6
// speedup vs baseline: 2.7832x; 1.0359x over previous
#include <cuda_runtime.h>
#include <math.h>
#include <stdint.h>

#define HH 128
#define WW 128
#define BB 8
#define CIN 64
#define COUT 64
#define HW (HH*WW)
#define NCH 27            // 18 offset channels + 9 mask channels
#define CSTR 68           // colT row stride in floats

// scratch (allocation-free: device globals)
__device__ float g_om[BB*NCH*HW];     // offsets + mask=2*sigmoid
__device__ float g_wT[9*64*64];       // [tap][cin][oc]

// ---------------------------------------------------------------------------
// packed fp32x2 helpers
// ---------------------------------------------------------------------------
__device__ __forceinline__ uint64_t pack2(float lo, float hi) {
    uint64_t r;
    asm("mov.b64 %0, {%1,%2};" : "=l"(r)
        : "r"(__float_as_uint(lo)), "r"(__float_as_uint(hi)));
    return r;
}
__device__ __forceinline__ void unpack2(uint64_t v, float& lo, float& hi) {
    uint32_t a, b;
    asm("mov.b64 {%0,%1}, %2;" : "=r"(a), "=r"(b) : "l"(v));
    lo = __uint_as_float(a); hi = __uint_as_float(b);
}
#define FFMA2(acc, a, b) \
    asm("fma.rn.f32x2 %0, %1, %2, %0;" : "+l"(acc) : "l"(a), "l"(b))

// ---------------------------------------------------------------------------
// Kernel 0: weight transform [oc][c][3][3] -> g_wT[t][c][oc]
// ---------------------------------------------------------------------------
__global__ void transpose_w_kernel(const float* __restrict__ w) {
    int idx = blockIdx.x * 256 + threadIdx.x;
    if (idx < 576 * COUT) {
        int oc  = idx / 576;
        int rem = idx % 576;
        int c   = rem / 9;
        int t   = rem % 9;
        g_wT[t * 4096 + c * 64 + oc] = w[idx];
    }
}

// ---------------------------------------------------------------------------
// Kernel 1: fused 3x3 conv -> 18 offsets + 9 masks (2*sigmoid).
// oc-pairs split across blockIdx.z (7 pairs each; pair 13 = oc26 + zero dummy).
// 2 output rows per block; smem-staged data. grid = (H/2, B, 2).
// ---------------------------------------------------------------------------
#define NPAIR 7

__global__ void __launch_bounds__(128, 4) conv_offmask_kernel(
    const float* __restrict__ data,
    const float* __restrict__ w_off, const float* __restrict__ b_off,
    const float* __restrict__ w_mod, const float* __restrict__ b_mod)
{
    __shared__ uint64_t wsp[NPAIR * 32 * 10];       // 17920 B
    __shared__ float    dtile[8 * 4 * 132];         // 16896 B

    const int h0 = blockIdx.x * 2;
    const int b  = blockIdx.y;
    const int pb = blockIdx.z * NPAIR;              // pair base (0 or 7)
    const int x  = threadIdx.x;

    // zero halo columns once
    if (threadIdx.x < 64) {
        int q = threadIdx.x >> 3;
        int r = (threadIdx.x >> 1) & 3;
        int s = threadIdx.x & 1;
        dtile[q * 528 + r * 132 + s * 129] = 0.0f;
    }

    uint64_t acc2[2][NPAIR];
#pragma unroll
    for (int p = 0; p < NPAIR; p++) {
        int ocA = 2 * (pb + p), ocB = ocA + 1;
        float bA = (ocA < 18) ? b_off[ocA] : b_mod[ocA - 18];
        float bB = (ocB < 18) ? b_off[ocB] : ((ocB < 27) ? b_mod[ocB - 18] : 0.0f);
        acc2[0][p] = pack2(bA, bB);
        acc2[1][p] = acc2[0][p];
    }

    for (int c0 = 0; c0 < CIN; c0 += 32) {
        __syncthreads();
        // stage paired weights for this 32-channel chunk (this z's pairs only)
        for (int idx = threadIdx.x; idx < NPAIR * 32 * 9; idx += 128) {
            int p  = idx / 288;
            int r  = idx % 288;
            int cc = r / 9;
            int k  = r % 9;
            int ocA = 2 * (pb + p), ocB = ocA + 1;
            const float* sA = (ocA < 18) ? (w_off + ocA * 576) : (w_mod + (ocA - 18) * 576);
            float vA = sA[(c0 + cc) * 9 + k];
            float vB = 0.0f;
            if (ocB < 27) {
                const float* sB = (ocB < 18) ? (w_off + ocB * 576) : (w_mod + (ocB - 18) * 576);
                vB = sB[(c0 + cc) * 9 + k];
            }
            wsp[(p * 32 + cc) * 10 + k] = pack2(vA, vB);
        }

        for (int cg = 0; cg < 4; cg++) {
            __syncthreads();
            const int cb = c0 + cg * 8;
#pragma unroll
            for (int q = 0; q < 8; q++) {
                const float* dp = data + ((size_t)(b * CIN + cb + q)) * HW;
#pragma unroll
                for (int r = 0; r < 4; r++) {
                    int hy = h0 - 1 + r;
                    float v = 0.0f;
                    if (hy >= 0 && hy < HH) v = dp[hy * WW + x];
                    dtile[q * 528 + r * 132 + 1 + x] = v;
                }
            }
            __syncthreads();

#pragma unroll
            for (int q = 0; q < 8; q++) {
                const int cc = cg * 8 + q;
                const float* dp = dtile + q * 528 + x;
                uint64_t dup[4][3];
#pragma unroll
                for (int r = 0; r < 4; r++)
#pragma unroll
                    for (int kx = 0; kx < 3; kx++) {
                        float v = dp[r * 132 + kx];
                        dup[r][kx] = pack2(v, v);
                    }

#pragma unroll
                for (int p = 0; p < NPAIR; p++) {
                    const uint64_t* base = wsp + (p * 32 + cc) * 10;
                    ulonglong2 w01 = *(const ulonglong2*)(base + 0);
                    ulonglong2 w23 = *(const ulonglong2*)(base + 2);
                    ulonglong2 w45 = *(const ulonglong2*)(base + 4);
                    ulonglong2 w67 = *(const ulonglong2*)(base + 6);
                    uint64_t   w8  = base[8];
                    FFMA2(acc2[0][p], dup[0][0], w01.x);
                    FFMA2(acc2[0][p], dup[0][1], w01.y);
                    FFMA2(acc2[0][p], dup[0][2], w23.x);
                    FFMA2(acc2[0][p], dup[1][0], w23.y);
                    FFMA2(acc2[0][p], dup[1][1], w45.x);
                    FFMA2(acc2[0][p], dup[1][2], w45.y);
                    FFMA2(acc2[0][p], dup[2][0], w67.x);
                    FFMA2(acc2[0][p], dup[2][1], w67.y);
                    FFMA2(acc2[0][p], dup[2][2], w8);
                    FFMA2(acc2[1][p], dup[1][0], w01.x);
                    FFMA2(acc2[1][p], dup[1][1], w01.y);
                    FFMA2(acc2[1][p], dup[1][2], w23.x);
                    FFMA2(acc2[1][p], dup[2][0], w23.y);
                    FFMA2(acc2[1][p], dup[2][1], w45.x);
                    FFMA2(acc2[1][p], dup[2][2], w45.y);
                    FFMA2(acc2[1][p], dup[3][0], w67.x);
                    FFMA2(acc2[1][p], dup[3][1], w67.y);
                    FFMA2(acc2[1][p], dup[3][2], w8);
                }
            }
        }
    }

#pragma unroll
    for (int rr = 0; rr < 2; rr++) {
        float* outp = g_om + ((size_t)(b * NCH) * HH + (h0 + rr)) * WW + x;
#pragma unroll
        for (int p = 0; p < NPAIR; p++) {
            float lo, hi;
            unpack2(acc2[rr][p], lo, hi);
            int ocA = 2 * (pb + p), ocB = ocA + 1;
            if (ocA >= 18) lo = 2.0f / (1.0f + expf(-lo));
            outp[ocA * HW] = lo;
            if (ocB < 27) {
                if (ocB >= 18) hi = 2.0f / (1.0f + expf(-hi));
                outp[ocB * HW] = hi;
            }
        }
    }
}

// ---------------------------------------------------------------------------
// Kernel 2: deform sample + GEMM, software-pipelined: gather for tap t+1 is
// interleaved (in 4 chunks) with the GEMM of tap t; wsm+colT double-buffered.
// block = 128 threads, 64 px, 64 oc. smem 67.6KB -> 3 blocks/SM.
// grid = (W/64, H, B)
// ---------------------------------------------------------------------------
#define DSM_BYTES (2*16384 + 2*17408)   // 67584

__global__ void __launch_bounds__(128, 3) deform_main_kernel(
    const float* __restrict__ data,
    const float* __restrict__ bias,
    float* __restrict__ out)
{
    extern __shared__ char dsm[];
    float* wsmA = (float*)dsm;                 // 2 x 4096 floats
    float* colA = (float*)(dsm + 32768);       // 2 x 4352 floats (64*CSTR)

    const int w0  = blockIdx.x * 64;
    const int h   = blockIdx.y;
    const int b   = blockIdx.z;
    const int tid = threadIdx.x;

    const float* dbase = data + (size_t)b * CIN * HW;

    const int i   = tid >> 4;            // oc group
    const int j   = tid & 15;            // px group
    const int oc0 = i * 8;

    const int gp = tid & 63;             // gather pixel
    const int gc = (tid >> 6) * 32;      // gather channel base
    const int x  = w0 + gp;

    const float* omb = g_om + ((size_t)(b * NCH) * HH + h) * WW + x;

    uint64_t acc[4][4];
#pragma unroll
    for (int p = 0; p < 4; p++)
#pragma unroll
        for (int q = 0; q < 4; q++) acc[p][q] = 0ULL;

    // ---- metadata computation (macro-ish lambda) ----
    auto compute_meta = [&](int t, float dy, float dx, float mk,
                            float& w00, float& w01, float& w10, float& w11,
                            int& i00, int& i01, int& i10, int& i11) {
        const float py = (float)(h - 1 + t / 3) + dy;
        const float px = (float)(x - 1 + t % 3) + dx;
        const float y0f = floorf(py), x0f = floorf(px);
        const float wy1 = py - y0f,  wx1 = px - x0f;
        const float wy0 = 1.0f - wy1, wx0 = 1.0f - wx1;
        const int y0 = (int)y0f, x0 = (int)x0f;
        const int y1 = y0 + 1,   x1 = x0 + 1;
        const bool vy0 = (y0 >= 0) && (y0 < HH);
        const bool vy1 = (y1 >= 0) && (y1 < HH);
        const bool vx0 = (x0 >= 0) && (x0 < WW);
        const bool vx1 = (x1 >= 0) && (x1 < WW);
        w00 = (vy0 && vx0) ? mk * wy0 * wx0 : 0.0f;
        w01 = (vy0 && vx1) ? mk * wy0 * wx1 : 0.0f;
        w10 = (vy1 && vx0) ? mk * wy1 * wx0 : 0.0f;
        w11 = (vy1 && vx1) ? mk * wy1 * wx1 : 0.0f;
        const int yc0 = min(max(y0, 0), HH - 1);
        const int yc1 = min(max(y1, 0), HH - 1);
        const int xc0 = min(max(x0, 0), WW - 1);
        const int xc1 = min(max(x1, 0), WW - 1);
        i00 = yc0 * WW + xc0;
        i01 = yc0 * WW + xc1;
        i10 = yc1 * WW + xc0;
        i11 = yc1 * WW + xc1;
    };

    // ---- prologue: tap 0 staged unpipelined ----
    {
        float dyC = omb[0], dxC = omb[HW], mkC = omb[18 * HW];
        const float4* wsrc = (const float4*)g_wT;
        float4* wdst = (float4*)wsmA;
#pragma unroll
        for (int r = 0; r < 8; r++) wdst[tid + r * 128] = wsrc[tid + r * 128];

        float w00, w01, w10, w11; int i00, i01, i10, i11;
        compute_meta(0, dyC, dxC, mkC, w00, w01, w10, w11, i00, i01, i10, i11);
        const float* d2 = dbase + (size_t)gc * HW;
        float* cp = colA + gc * CSTR + gp;
#pragma unroll 8
        for (int cc = 0; cc < 32; cc++) {
            float v = w00 * d2[i00];
            v = fmaf(w01, d2[i01], v);
            v = fmaf(w10, d2[i10], v);
            v = fmaf(w11, d2[i11], v);
            cp[cc * CSTR] = v;
            d2 += HW;
        }
    }
    // prefetch metadata for tap 1
    float dyN = omb[2 * HW], dxN = omb[3 * HW], mkN = omb[19 * HW];
    __syncthreads();

    // ---- main pipelined loop ----
#pragma unroll 1
    for (int t = 0; t < 9; t++) {
        const int cur = t & 1, nxt = cur ^ 1;
        const bool more = (t < 8);

        float w00 = 0, w01 = 0, w10 = 0, w11 = 0;
        int i00 = 0, i01 = 0, i10 = 0, i11 = 0;
        if (more) {
            compute_meta(t + 1, dyN, dxN, mkN, w00, w01, w10, w11, i00, i01, i10, i11);
            if (t + 2 < 9) {
                dyN = omb[2 * (t + 2) * HW];
                dxN = omb[(2 * (t + 2) + 1) * HW];
                mkN = omb[(18 + t + 2) * HW];
            }
        }

        const float* wrow = wsmA + cur * 4096 + oc0;
        const float* crow = colA + cur * 4352 + j * 4;
        const float4* wsrc = (const float4*)(g_wT + (more ? (t + 1) : 0) * 4096);
        float4* wdst = (float4*)(wsmA + nxt * 4096);
        float* cpn = colA + nxt * 4352 + gc * CSTR + gp;

#pragma unroll 1
        for (int q = 0; q < 4; q++) {
            float4 wrA, wrB;
            float g[32];
            if (more) {
                wrA = wsrc[tid + (2 * q) * 128];
                wrB = wsrc[tid + (2 * q + 1) * 128];
                const float* dq = dbase + (size_t)(gc + q * 8) * HW;
#pragma unroll
                for (int cc = 0; cc < 8; cc++) {
                    g[4 * cc + 0] = dq[i00];
                    g[4 * cc + 1] = dq[i01];
                    g[4 * cc + 2] = dq[i10];
                    g[4 * cc + 3] = dq[i11];
                    dq += HW;
                }
            }

            const float* wk = wrow + q * 16 * 64;
            const float* ck = crow + q * 16 * CSTR;
#pragma unroll
            for (int kl = 0; kl < 16; kl++) {
                ulonglong2 wA = *(const ulonglong2*)(wk + kl * 64);
                ulonglong2 wB = *(const ulonglong2*)(wk + kl * 64 + 4);
                float4 cv = *(const float4*)(ck + kl * CSTR);
                uint64_t c0 = pack2(cv.x, cv.x);
                uint64_t c1 = pack2(cv.y, cv.y);
                uint64_t c2 = pack2(cv.z, cv.z);
                uint64_t c3 = pack2(cv.w, cv.w);
                FFMA2(acc[0][0], wA.x, c0); FFMA2(acc[0][1], wA.x, c1);
                FFMA2(acc[0][2], wA.x, c2); FFMA2(acc[0][3], wA.x, c3);
                FFMA2(acc[1][0], wA.y, c0); FFMA2(acc[1][1], wA.y, c1);
                FFMA2(acc[1][2], wA.y, c2); FFMA2(acc[1][3], wA.y, c3);
                FFMA2(acc[2][0], wB.x, c0); FFMA2(acc[2][1], wB.x, c1);
                FFMA2(acc[2][2], wB.x, c2); FFMA2(acc[2][3], wB.x, c3);
                FFMA2(acc[3][0], wB.y, c0); FFMA2(acc[3][1], wB.y, c1);
                FFMA2(acc[3][2], wB.y, c2); FFMA2(acc[3][3], wB.y, c3);
            }

            if (more) {
                wdst[tid + (2 * q) * 128] = wrA;
                wdst[tid + (2 * q + 1) * 128] = wrB;
#pragma unroll
                for (int cc = 0; cc < 8; cc++) {
                    float v = w00 * g[4 * cc + 0];
                    v = fmaf(w01, g[4 * cc + 1], v);
                    v = fmaf(w10, g[4 * cc + 2], v);
                    v = fmaf(w11, g[4 * cc + 3], v);
                    cpn[(q * 8 + cc) * CSTR] = v;
                }
            }
        }
        __syncthreads();
    }

    // ---- epilogue: bias + relu + float4 stores ----
#pragma unroll
    for (int p = 0; p < 4; p++) {
        const int ocA = oc0 + 2 * p;
        const float bA = bias[ocA];
        const float bB = bias[ocA + 1];
        float a0, b0, a1, b1, a2, b2, a3, b3;
        unpack2(acc[p][0], a0, b0);
        unpack2(acc[p][1], a1, b1);
        unpack2(acc[p][2], a2, b2);
        unpack2(acc[p][3], a3, b3);
        float* obA = out + (((size_t)(b * COUT + ocA)) * HH + h) * WW + w0 + j * 4;
        float4 rA = make_float4(fmaxf(a0 + bA, 0.f), fmaxf(a1 + bA, 0.f),
                                fmaxf(a2 + bA, 0.f), fmaxf(a3 + bA, 0.f));
        *(float4*)obA = rA;
        float4 rB = make_float4(fmaxf(b0 + bB, 0.f), fmaxf(b1 + bB, 0.f),
                                fmaxf(b2 + bB, 0.f), fmaxf(b3 + bB, 0.f));
        *(float4*)(obA + HW) = rB;
    }
}

// ---------------------------------------------------------------------------
extern "C" void kernel_launch(void* const* d_in, const int* in_sizes, int n_in,
                              void* d_out, int out_size)
{
    const float* data  = (const float*)d_in[0];
    const float* w     = (const float*)d_in[1];
    const float* bias  = (const float*)d_in[2];
    const float* w_off = (const float*)d_in[3];
    const float* b_off = (const float*)d_in[4];
    const float* w_mod = (const float*)d_in[5];
    const float* b_mod = (const float*)d_in[6];
    float* out = (float*)d_out;

    cudaFuncSetAttribute(deform_main_kernel,
                         cudaFuncAttributeMaxDynamicSharedMemorySize, DSM_BYTES);

    conv_offmask_kernel<<<dim3(HH / 2, BB, 2), 128>>>(data, w_off, b_off, w_mod, b_mod);
    transpose_w_kernel<<<144, 256>>>(w);
    deform_main_kernel<<<dim3(WW / 64, HH, BB), 128, DSM_BYTES>>>(data, bias, out);
}